// round 4
// baseline (speedup 1.0000x reference)
#include <cuda_runtime.h>

#define W_g 200
#define H_g 200
#define NQ 40000
#define Dm 256
#define M_ROWS 40000

// Scratch (no allocations allowed)
__device__ float g_v[NQ * Dm];      // value @ W_v + b_v   (40000 x 256)
__device__ float g_soaw[NQ * 192];  // cols 0..127 = so, 128..191 = aw (pre-softmax)
__device__ float g_mid[NQ * Dm];    // deform-attn output  (40000 x 256)

// ---------------------------------------------------------------------------
// Double-buffered SGEMM, BM=128, BN in {128, 64}, BK=16, 8x8 microtile.
// NT = (128/8)*(BN/8) threads. C[m, c0+bn+n] = A' @ B + bias.
// A' = A (MxK, row stride K) or virtual [A | A+A2] (K=512, phys stride 256).
// B row stride = Nb. Ragged last row-tile handled by clamp/predication.
// ---------------------------------------------------------------------------
template <int BN, bool CONCAT>
__global__ __launch_bounds__(16 * (BN / 8)) void sgemm128(
    const float* __restrict__ A, const float* __restrict__ A2,
    const float* __restrict__ B, const float* __restrict__ bias,
    float* __restrict__ C, int K, int Nb, int ldC, int c0)
{
    constexpr int NT     = 16 * (BN / 8);   // threads
    constexpr int AL     = 512 / NT;        // A float4 loads / thread
    constexpr int BCOLS4 = BN / 4;
    constexpr int BL     = (16 * BCOLS4) / NT;  // B float4 loads / thread

    __shared__ float As[2][16][132];
    __shared__ float Bs[2][16][BN];

    const int tid = threadIdx.x;
    const int bm  = blockIdx.y * 128;
    const int bn  = blockIdx.x * BN;
    const int tx  = tid % (BN / 8);
    const int ty  = tid / (BN / 8);

    float acc[8][8];
    #pragma unroll
    for (int i = 0; i < 8; ++i)
        #pragma unroll
        for (int j = 0; j < 8; ++j) acc[i][j] = 0.f;

    float4 ar[AL], br[BL];

    auto ldg_tile = [&](int t) {
        const int k0 = t << 4;
        #pragma unroll
        for (int i = 0; i < AL; ++i) {
            const int flat = i * NT + tid;
            const int r = flat >> 2;
            const int c = (flat & 3) << 2;
            const int row = min(bm + r, M_ROWS - 1);
            if (!CONCAT) {
                ar[i] = *reinterpret_cast<const float4*>(&A[(size_t)row * K + k0 + c]);
            } else if (k0 < 256) {
                ar[i] = *reinterpret_cast<const float4*>(&A[(size_t)row * 256 + k0 + c]);
            } else {
                const int kk = k0 - 256;
                float4 p = *reinterpret_cast<const float4*>(&A [(size_t)row * 256 + kk + c]);
                float4 qv = *reinterpret_cast<const float4*>(&A2[(size_t)row * 256 + kk + c]);
                ar[i] = make_float4(p.x + qv.x, p.y + qv.y, p.z + qv.z, p.w + qv.w);
            }
        }
        #pragma unroll
        for (int i = 0; i < BL; ++i) {
            const int flat = i * NT + tid;
            const int brow = flat / BCOLS4;
            const int bcol = (flat % BCOLS4) << 2;
            br[i] = *reinterpret_cast<const float4*>(&B[(size_t)(k0 + brow) * Nb + bn + bcol]);
        }
    };

    auto sts_tile = [&](int buf) {
        #pragma unroll
        for (int i = 0; i < AL; ++i) {
            const int flat = i * NT + tid;
            const int r = flat >> 2;
            const int c = (flat & 3) << 2;
            As[buf][c + 0][r] = ar[i].x;
            As[buf][c + 1][r] = ar[i].y;
            As[buf][c + 2][r] = ar[i].z;
            As[buf][c + 3][r] = ar[i].w;
        }
        #pragma unroll
        for (int i = 0; i < BL; ++i) {
            const int flat = i * NT + tid;
            const int brow = flat / BCOLS4;
            const int bcol = (flat % BCOLS4) << 2;
            *reinterpret_cast<float4*>(&Bs[buf][brow][bcol]) = br[i];
        }
    };

    const int ntiles = K >> 4;
    ldg_tile(0);
    sts_tile(0);
    __syncthreads();

    for (int t = 0; t < ntiles; ++t) {
        const int cur = t & 1;
        if (t + 1 < ntiles) ldg_tile(t + 1);

        #pragma unroll
        for (int k = 0; k < 16; ++k) {
            float4 a0 = *reinterpret_cast<const float4*>(&As[cur][k][ty * 8]);
            float4 a1 = *reinterpret_cast<const float4*>(&As[cur][k][ty * 8 + 4]);
            float4 b0 = *reinterpret_cast<const float4*>(&Bs[cur][k][tx * 8]);
            float4 b1 = *reinterpret_cast<const float4*>(&Bs[cur][k][tx * 8 + 4]);
            float a[8] = {a0.x, a0.y, a0.z, a0.w, a1.x, a1.y, a1.z, a1.w};
            float b[8] = {b0.x, b0.y, b0.z, b0.w, b1.x, b1.y, b1.z, b1.w};
            #pragma unroll
            for (int i = 0; i < 8; ++i)
                #pragma unroll
                for (int j = 0; j < 8; ++j)
                    acc[i][j] = fmaf(a[i], b[j], acc[i][j]);
        }

        if (t + 1 < ntiles) {
            sts_tile(1 - cur);
            __syncthreads();
        }
    }

    // ---- epilogue: bias + predicated store ----
    float bb[8];
    #pragma unroll
    for (int j = 0; j < 8; ++j) bb[j] = bias[bn + tx * 8 + j];
    #pragma unroll
    for (int i = 0; i < 8; ++i) {
        const int row = bm + ty * 8 + i;
        if (row < M_ROWS) {
            float4 o0 = make_float4(acc[i][0] + bb[0], acc[i][1] + bb[1],
                                    acc[i][2] + bb[2], acc[i][3] + bb[3]);
            float4 o1 = make_float4(acc[i][4] + bb[4], acc[i][5] + bb[5],
                                    acc[i][6] + bb[6], acc[i][7] + bb[7]);
            float* cp = &C[(size_t)row * ldC + c0 + bn + tx * 8];
            *reinterpret_cast<float4*>(cp)     = o0;
            *reinterpret_cast<float4*>(cp + 4) = o1;
        }
    }
}

// ---------------------------------------------------------------------------
// Deformable sampling, two-phase (unchanged from R2/R3).
// ---------------------------------------------------------------------------
__global__ __launch_bounds__(256) void deform_kernel(
    const float* __restrict__ v, const float* __restrict__ soaw,
    const float* __restrict__ ref, float* __restrict__ outm)
{
    __shared__ float4 s_w[64];
    __shared__ int4   s_idx[64];

    const int q   = blockIdx.x;
    const int tid = threadIdx.x;

    if (tid < 64) {
        const int h  = tid >> 3;
        const int qq = (tid >> 2) & 1;
        const int p  = tid & 3;
        const float* srow = soaw + (size_t)q * 192;

        const float rpx = ref[q * 2 + 0];
        const float rpy = ref[q * 2 + 1];

        const float sx = srow[h * 16 + qq * 8 + p * 2 + 0];
        const float sy = srow[h * 16 + qq * 8 + p * 2 + 1];
        float a        = srow[128 + h * 8 + qq * 4 + p];

        float m = fmaxf(a, __shfl_xor_sync(0xffffffffu, a, 1));
        m = fmaxf(m, __shfl_xor_sync(0xffffffffu, m, 2));
        float e = __expf(a - m);
        float s = e + __shfl_xor_sync(0xffffffffu, e, 1);
        s = s + __shfl_xor_sync(0xffffffffu, s, 2);
        const float wt = 0.5f * e / s;

        const float x = fmaf(rpx, (float)W_g, sx) - 0.5f;
        const float y = fmaf(rpy, (float)H_g, sy) - 0.5f;
        const float x0f = floorf(x), y0f = floorf(y);
        const int   x0 = (int)x0f,  y0 = (int)y0f;
        const float wx1 = x - x0f, wx0 = 1.f - wx1;
        const float wy1 = y - y0f, wy0 = 1.f - wy1;

        const bool vx0 = (x0 >= 0) && (x0 < W_g);
        const bool vx1 = (x0 + 1 >= 0) && (x0 + 1 < W_g);
        const bool vy0 = (y0 >= 0) && (y0 < H_g);
        const bool vy1 = (y0 + 1 >= 0) && (y0 + 1 < H_g);
        const int cx0 = min(max(x0, 0),     W_g - 1);
        const int cx1 = min(max(x0 + 1, 0), W_g - 1);
        const int cy0 = min(max(y0, 0),     H_g - 1);
        const int cy1 = min(max(y0 + 1, 0), H_g - 1);

        float4 w;
        w.x = wt * wx0 * wy0 * (float)(vx0 && vy0);
        w.y = wt * wx1 * wy0 * (float)(vx1 && vy0);
        w.z = wt * wx0 * wy1 * (float)(vx0 && vy1);
        w.w = wt * wx1 * wy1 * (float)(vx1 && vy1);

        int4 ix;
        ix.x = (cy0 * W_g + cx0) * (Dm * 4);
        ix.y = (cy0 * W_g + cx1) * (Dm * 4);
        ix.z = (cy1 * W_g + cx0) * (Dm * 4);
        ix.w = (cy1 * W_g + cx1) * (Dm * 4);

        s_w[tid]   = w;
        s_idx[tid] = ix;
    }
    __syncthreads();

    const int h    = tid >> 5;
    const int lane = tid & 31;
    const char* vh = (const char*)(v + h * 32 + lane);

    float acc = 0.f;
    #pragma unroll
    for (int pp = 0; pp < 8; ++pp) {
        const int t = h * 8 + pp;
        const float4 w  = s_w[t];
        const int4   ix = s_idx[t];
        acc = fmaf(w.x, *(const float*)(vh + ix.x), acc);
        acc = fmaf(w.y, *(const float*)(vh + ix.y), acc);
        acc = fmaf(w.z, *(const float*)(vh + ix.z), acc);
        acc = fmaf(w.w, *(const float*)(vh + ix.w), acc);
    }

    outm[(size_t)q * Dm + h * 32 + lane] = acc;
}

// ---------------------------------------------------------------------------
extern "C" void kernel_launch(void* const* d_in, const int* in_sizes, int n_in,
                              void* d_out, int out_size)
{
    const float* query     = (const float*)d_in[0];
    const float* query_pos = (const float*)d_in[1];
    const float* refpts    = (const float*)d_in[2];
    const float* W_so      = (const float*)d_in[3];
    const float* b_so      = (const float*)d_in[4];
    const float* W_aw      = (const float*)d_in[5];
    const float* b_aw      = (const float*)d_in[6];
    const float* W_v       = (const float*)d_in[7];
    const float* b_v       = (const float*)d_in[8];
    const float* W_o       = (const float*)d_in[9];
    const float* b_o       = (const float*)d_in[10];
    float* out = (float*)d_out;

    float *gv, *gsoaw, *gmid;
    cudaGetSymbolAddress((void**)&gv,    g_v);
    cudaGetSymbolAddress((void**)&gsoaw, g_soaw);
    cudaGetSymbolAddress((void**)&gmid,  g_mid);

    const int gy = (M_ROWS + 127) / 128;   // 313

    // v = query @ W_v + b_v              (K=256, N=256)
    sgemm128<128, false><<<dim3(2, gy), 256>>>(query, nullptr, W_v, b_v, gv, 256, 256, 256, 0);
    // so = [q | q+pos] @ W_so + b_so     (K=512, N=128) -> soaw cols 0..127
    sgemm128<128, true><<<dim3(1, gy), 256>>>(query, query_pos, W_so, b_so, gsoaw, 512, 128, 192, 0);
    // aw = [q | q+pos] @ W_aw + b_aw     (K=512, N=64)  -> soaw cols 128..191
    sgemm128<64, true><<<dim3(1, gy), 128>>>(query, query_pos, W_aw, b_aw, gsoaw, 512, 64, 192, 128);
    // deformable attention sampling
    deform_kernel<<<NQ, 256>>>(gv, gsoaw, refpts, gmid);
    // out = mid @ W_o + b_o              (K=256, N=256)
    sgemm128<128, false><<<dim3(2, gy), 256>>>(gmid, nullptr, W_o, b_o, out, 256, 256, 256, 0);
}

// round 6
// speedup vs baseline: 1.5284x; 1.5284x over previous
#include <cuda_runtime.h>
#include <cuda_bf16.h>
#include <cstdint>

#define W_g 200
#define H_g 200
#define NQ 40000
#define Dm 256
#define M_ROWS 40000

// ---------------------------------------------------------------------------
// Device scratch (no allocations allowed)
// ---------------------------------------------------------------------------
__device__ float g_v[NQ * Dm];        // v = value @ W_v + b_v (fp32, deform input)
__device__ float g_soaw[NQ * 192];    // cols 0..127 so, 128..191 aw (pre-softmax)
__device__ __nv_bfloat16 g_qcat_hi[NQ * 512];  // [q | q+pos] split-high
__device__ __nv_bfloat16 g_qcat_lo[NQ * 512];  // split-low
__device__ __nv_bfloat16 g_mid_hi[NQ * 256];
__device__ __nv_bfloat16 g_mid_lo[NQ * 256];
__device__ __nv_bfloat16 g_wv_hi[256 * 256],  g_wv_lo[256 * 256];     // [n][k]
__device__ __nv_bfloat16 g_wsa_hi[192 * 512], g_wsa_lo[192 * 512];    // W_so|W_aw, [n][k]
__device__ __nv_bfloat16 g_wo_hi[256 * 256],  g_wo_lo[256 * 256];     // [n][k]

__device__ __forceinline__ uint32_t smem_u32(const void* p) {
    uint32_t a;
    asm("{ .reg .u64 t; cvta.to.shared.u64 t, %1; cvt.u32.u64 %0, t; }" : "=r"(a) : "l"(p));
    return a;
}
__device__ __forceinline__ void bsplit(float x, __nv_bfloat16& h, __nv_bfloat16& l) {
    h = __float2bfloat16(x);
    l = __float2bfloat16(x - __bfloat162float(h));
}
__device__ __forceinline__ void ldmatrix_x4(uint32_t* r, uint32_t addr) {
    asm volatile("ldmatrix.sync.aligned.m8n8.x4.shared.b16 {%0,%1,%2,%3}, [%4];"
                 : "=r"(r[0]), "=r"(r[1]), "=r"(r[2]), "=r"(r[3]) : "r"(addr));
}
__device__ __forceinline__ void mma_16816(float* c, const uint32_t* a, const uint32_t* b) {
    asm volatile(
        "mma.sync.aligned.m16n8k16.row.col.f32.bf16.bf16.f32 "
        "{%0,%1,%2,%3}, {%4,%5,%6,%7}, {%8,%9}, {%0,%1,%2,%3};"
        : "+f"(c[0]), "+f"(c[1]), "+f"(c[2]), "+f"(c[3])
        : "r"(a[0]), "r"(a[1]), "r"(a[2]), "r"(a[3]), "r"(b[0]), "r"(b[1]));
}

// ---------------------------------------------------------------------------
// Split-bf16 GEMM via mma.sync.  C[m, n] = sum_k A[m,k]*Bt[n,k] + bias(n)
// Virtual K = 3 segments: (Ahi,Bhi), (Alo,Bhi), (Ahi,Blo).
// Block 128x128, BK=32, 256 threads (8 warps 2x4, warp tile 64x32).
// SMEM rows padded to 80 B for conflict-free ldmatrix.
// ---------------------------------------------------------------------------
__global__ __launch_bounds__(256) void gemm_mma(
    const __nv_bfloat16* __restrict__ Ahi, const __nv_bfloat16* __restrict__ Alo, int ldA,
    const __nv_bfloat16* __restrict__ Bhi, const __nv_bfloat16* __restrict__ Blo,
    int K, int Nb,
    const float* __restrict__ bias0, const float* __restrict__ bias1, int nsplit,
    float* __restrict__ C, int ldC)
{
    __shared__ __align__(16) uint8_t sA[2][128 * 80];
    __shared__ __align__(16) uint8_t sB[2][128 * 80];

    const int tid  = threadIdx.x;
    const int lane = tid & 31;
    const int wid  = tid >> 5;
    const int wr   = wid >> 2;        // 0..1 : warp row (64 rows)
    const int wc   = wid & 3;         // 0..3 : warp col (32 cols)
    const int bm   = blockIdx.y * 128;
    const int bn   = blockIdx.x * 128;

    float acc[4][4][4];
    #pragma unroll
    for (int i = 0; i < 4; ++i)
        #pragma unroll
        for (int j = 0; j < 4; ++j)
            #pragma unroll
            for (int k = 0; k < 4; ++k) acc[i][j][k] = 0.f;

    const int kchunks = K >> 5;       // chunks per segment
    const int nc = 3 * kchunks;

    uint4 ra[2], rb[2];

    auto ldg_chunk = [&](int c) {
        const int seg = c / kchunks;
        const int k0  = (c - seg * kchunks) << 5;
        const __nv_bfloat16* Ap = (seg == 1) ? Alo : Ahi;
        const __nv_bfloat16* Bp = (seg == 2) ? Blo : Bhi;
        #pragma unroll
        for (int i = 0; i < 2; ++i) {
            const int s = tid + i * 256;
            const int row = s >> 2, g = s & 3;
            ra[i] = *(const uint4*)(Ap + (size_t)min(bm + row, M_ROWS - 1) * ldA + k0 + g * 8);
            rb[i] = *(const uint4*)(Bp + (size_t)min(bn + row, Nb - 1)   * K   + k0 + g * 8);
        }
    };
    auto sts_chunk = [&](int buf) {
        #pragma unroll
        for (int i = 0; i < 2; ++i) {
            const int s = tid + i * 256;
            const int row = s >> 2, g = s & 3;
            *(uint4*)(sA[buf] + row * 80 + g * 16) = ra[i];
            *(uint4*)(sB[buf] + row * 80 + g * 16) = rb[i];
        }
    };

    // lane address components (ldmatrix.x4, non-trans, both operands)
    const int a_r  = (((lane >> 3) & 1) << 3) + (lane & 7);   // row within 16
    const int a_c  = (lane >> 4) << 3;                        // k offset (0/8)
    const int b_r  = ((lane >> 4) << 3) + (lane & 7);         // row within 16
    const int b_c  = ((lane >> 3) & 1) << 3;                  // k offset (0/8)

    ldg_chunk(0);
    sts_chunk(0);
    __syncthreads();

    for (int c = 0; c < nc; ++c) {
        const int cur = c & 1;
        if (c + 1 < nc) ldg_chunk(c + 1);

        const uint32_t baseA = smem_u32(sA[cur]);
        const uint32_t baseB = smem_u32(sB[cur]);

        #pragma unroll
        for (int kk = 0; kk < 32; kk += 16) {
            uint32_t af[4][4];
            #pragma unroll
            for (int mc = 0; mc < 4; ++mc) {
                const uint32_t addr = baseA + (wr * 64 + mc * 16 + a_r) * 80 + (kk + a_c) * 2;
                ldmatrix_x4(af[mc], addr);
            }
            uint32_t bf[4][2];
            #pragma unroll
            for (int jj = 0; jj < 2; ++jj) {
                uint32_t r[4];
                const uint32_t addr = baseB + (wc * 32 + jj * 16 + b_r) * 80 + (kk + b_c) * 2;
                ldmatrix_x4(r, addr);
                bf[jj * 2 + 0][0] = r[0]; bf[jj * 2 + 0][1] = r[1];
                bf[jj * 2 + 1][0] = r[2]; bf[jj * 2 + 1][1] = r[3];
            }
            #pragma unroll
            for (int mc = 0; mc < 4; ++mc)
                #pragma unroll
                for (int ncn = 0; ncn < 4; ++ncn)
                    mma_16816(acc[mc][ncn], af[mc], bf[ncn]);
        }

        if (c + 1 < nc) {
            sts_chunk(1 - cur);
            __syncthreads();
        }
    }

    // ---- epilogue ----
    const int gid = lane >> 2, tig = lane & 3;
    #pragma unroll
    for (int mc = 0; mc < 4; ++mc) {
        #pragma unroll
        for (int ncn = 0; ncn < 4; ++ncn) {
            const int n0 = bn + wc * 32 + ncn * 8 + tig * 2;
            if (n0 >= Nb) continue;
            const float bx = (n0     < nsplit) ? bias0[n0]     : bias1[n0 - nsplit];
            const float by = (n0 + 1 < nsplit) ? bias0[n0 + 1] : bias1[n0 + 1 - nsplit];
            const int m0 = bm + wr * 64 + mc * 16 + gid;
            if (m0 < M_ROWS) {
                float2 o = make_float2(acc[mc][ncn][0] + bx, acc[mc][ncn][1] + by);
                *(float2*)&C[(size_t)m0 * ldC + n0] = o;
            }
            if (m0 + 8 < M_ROWS) {
                float2 o = make_float2(acc[mc][ncn][2] + bx, acc[mc][ncn][3] + by);
                *(float2*)&C[(size_t)(m0 + 8) * ldC + n0] = o;
            }
        }
    }
}

// ---------------------------------------------------------------------------
// Conversion kernels
// ---------------------------------------------------------------------------
__global__ void conv_q(const float* __restrict__ q, const float* __restrict__ qp,
                       __nv_bfloat16* __restrict__ chi, __nv_bfloat16* __restrict__ clo)
{
    for (int i = blockIdx.x * blockDim.x + threadIdx.x; i < NQ * 256;
         i += gridDim.x * blockDim.x) {
        const int row = i >> 8, c = i & 255;
        __nv_bfloat16 h, l;
        const float a = q[i];
        bsplit(a, h, l);
        chi[(size_t)row * 512 + c] = h;  clo[(size_t)row * 512 + c] = l;
        const float b = a + qp[i];
        bsplit(b, h, l);
        chi[(size_t)row * 512 + 256 + c] = h;  clo[(size_t)row * 512 + 256 + c] = l;
    }
}

// out[(nOff+n)*ldOut + k] = split(W[k*Ndim + n])   (transpose K x N -> [n][k])
__global__ void conv_w(const float* __restrict__ W, __nv_bfloat16* __restrict__ hi,
                       __nv_bfloat16* __restrict__ lo, int Kdim, int Ndim, int nOff, int ldOut)
{
    for (int i = blockIdx.x * blockDim.x + threadIdx.x; i < Kdim * Ndim;
         i += gridDim.x * blockDim.x) {
        const int k = i / Ndim, n = i % Ndim;
        __nv_bfloat16 h, l;
        bsplit(W[i], h, l);
        hi[(size_t)(nOff + n) * ldOut + k] = h;
        lo[(size_t)(nOff + n) * ldOut + k] = l;
    }
}

// ---------------------------------------------------------------------------
// Deformable sampling, two-phase; emits split-bf16 mid.
// ---------------------------------------------------------------------------
__global__ __launch_bounds__(256) void deform_kernel(
    const float* __restrict__ v, const float* __restrict__ soaw,
    const float* __restrict__ ref,
    __nv_bfloat16* __restrict__ mhi, __nv_bfloat16* __restrict__ mlo)
{
    __shared__ float4 s_w[64];
    __shared__ int4   s_idx[64];

    const int q   = blockIdx.x;
    const int tid = threadIdx.x;

    if (tid < 64) {
        const int h  = tid >> 3;
        const int qq = (tid >> 2) & 1;
        const int p  = tid & 3;
        const float* srow = soaw + (size_t)q * 192;

        const float rpx = ref[q * 2 + 0];
        const float rpy = ref[q * 2 + 1];

        const float sx = srow[h * 16 + qq * 8 + p * 2 + 0];
        const float sy = srow[h * 16 + qq * 8 + p * 2 + 1];
        float a        = srow[128 + h * 8 + qq * 4 + p];

        float m = fmaxf(a, __shfl_xor_sync(0xffffffffu, a, 1));
        m = fmaxf(m, __shfl_xor_sync(0xffffffffu, m, 2));
        float e = __expf(a - m);
        float s = e + __shfl_xor_sync(0xffffffffu, e, 1);
        s = s + __shfl_xor_sync(0xffffffffu, s, 2);
        const float wt = 0.5f * e / s;

        const float x = fmaf(rpx, (float)W_g, sx) - 0.5f;
        const float y = fmaf(rpy, (float)H_g, sy) - 0.5f;
        const float x0f = floorf(x), y0f = floorf(y);
        const int   x0 = (int)x0f,  y0 = (int)y0f;
        const float wx1 = x - x0f, wx0 = 1.f - wx1;
        const float wy1 = y - y0f, wy0 = 1.f - wy1;

        const bool vx0 = (x0 >= 0) && (x0 < W_g);
        const bool vx1 = (x0 + 1 >= 0) && (x0 + 1 < W_g);
        const bool vy0 = (y0 >= 0) && (y0 < H_g);
        const bool vy1 = (y0 + 1 >= 0) && (y0 + 1 < H_g);
        const int cx0 = min(max(x0, 0),     W_g - 1);
        const int cx1 = min(max(x0 + 1, 0), W_g - 1);
        const int cy0 = min(max(y0, 0),     H_g - 1);
        const int cy1 = min(max(y0 + 1, 0), H_g - 1);

        float4 w;
        w.x = wt * wx0 * wy0 * (float)(vx0 && vy0);
        w.y = wt * wx1 * wy0 * (float)(vx1 && vy0);
        w.z = wt * wx0 * wy1 * (float)(vx0 && vy1);
        w.w = wt * wx1 * wy1 * (float)(vx1 && vy1);

        int4 ix;
        ix.x = (cy0 * W_g + cx0) * (Dm * 4);
        ix.y = (cy0 * W_g + cx1) * (Dm * 4);
        ix.z = (cy1 * W_g + cx0) * (Dm * 4);
        ix.w = (cy1 * W_g + cx1) * (Dm * 4);

        s_w[tid]   = w;
        s_idx[tid] = ix;
    }
    __syncthreads();

    const int h    = tid >> 5;
    const int lane = tid & 31;
    const char* vh = (const char*)(v + h * 32 + lane);

    float acc = 0.f;
    #pragma unroll
    for (int pp = 0; pp < 8; ++pp) {
        const int t = h * 8 + pp;
        const float4 w  = s_w[t];
        const int4   ix = s_idx[t];
        acc = fmaf(w.x, *(const float*)(vh + ix.x), acc);
        acc = fmaf(w.y, *(const float*)(vh + ix.y), acc);
        acc = fmaf(w.z, *(const float*)(vh + ix.z), acc);
        acc = fmaf(w.w, *(const float*)(vh + ix.w), acc);
    }

    __nv_bfloat16 hi, lo;
    bsplit(acc, hi, lo);
    const size_t oi = (size_t)q * Dm + h * 32 + lane;
    mhi[oi] = hi;
    mlo[oi] = lo;
}

// ---------------------------------------------------------------------------
extern "C" void kernel_launch(void* const* d_in, const int* in_sizes, int n_in,
                              void* d_out, int out_size)
{
    const float* query     = (const float*)d_in[0];
    const float* query_pos = (const float*)d_in[1];
    const float* refpts    = (const float*)d_in[2];
    const float* W_so      = (const float*)d_in[3];
    const float* b_so      = (const float*)d_in[4];
    const float* W_aw      = (const float*)d_in[5];
    const float* b_aw      = (const float*)d_in[6];
    const float* W_v       = (const float*)d_in[7];
    const float* b_v       = (const float*)d_in[8];
    const float* W_o       = (const float*)d_in[9];
    const float* b_o       = (const float*)d_in[10];
    float* out = (float*)d_out;

    float *gv, *gsoaw;
    __nv_bfloat16 *qh, *ql, *mh, *ml, *wvh, *wvl, *wsh, *wsl, *woh, *wol;
    cudaGetSymbolAddress((void**)&gv,    g_v);
    cudaGetSymbolAddress((void**)&gsoaw, g_soaw);
    cudaGetSymbolAddress((void**)&qh,  g_qcat_hi);
    cudaGetSymbolAddress((void**)&ql,  g_qcat_lo);
    cudaGetSymbolAddress((void**)&mh,  g_mid_hi);
    cudaGetSymbolAddress((void**)&ml,  g_mid_lo);
    cudaGetSymbolAddress((void**)&wvh, g_wv_hi);
    cudaGetSymbolAddress((void**)&wvl, g_wv_lo);
    cudaGetSymbolAddress((void**)&wsh, g_wsa_hi);
    cudaGetSymbolAddress((void**)&wsl, g_wsa_lo);
    cudaGetSymbolAddress((void**)&woh, g_wo_hi);
    cudaGetSymbolAddress((void**)&wol, g_wo_lo);

    const int gm = (M_ROWS + 127) / 128;  // 313

    // conversions
    conv_q<<<4096, 256>>>(query, query_pos, qh, ql);
    conv_w<<<256, 256>>>(W_v,  wvh, wvl, 256, 256, 0,   256);
    conv_w<<<256, 256>>>(W_so, wsh, wsl, 512, 128, 0,   512);
    conv_w<<<128, 256>>>(W_aw, wsh, wsl, 512, 64,  128, 512);
    conv_w<<<256, 256>>>(W_o,  woh, wol, 256, 256, 0,   256);

    // G1: v = query @ W_v + b_v   (A = qcat cols 0..255, ldA = 512)
    gemm_mma<<<dim3(2, gm), 256>>>(qh, ql, 512, wvh, wvl, 256, 256, b_v, b_v, 256, gv, 256);
    // G2: soaw = [q | q+pos] @ [W_so | W_aw] + bias   (K=512, Nb=192)
    gemm_mma<<<dim3(2, gm), 256>>>(qh, ql, 512, wsh, wsl, 512, 192, b_so, b_aw, 128, gsoaw, 192);
    // deform (emits split-bf16 mid)
    deform_kernel<<<NQ, 256>>>(gv, gsoaw, refpts, mh, ml);
    // G3: out = mid @ W_o + b_o
    gemm_mma<<<dim3(2, gm), 256>>>(mh, ml, 256, woh, wol, 256, 256, b_o, b_o, 256, out, 256);
}

// round 7
// speedup vs baseline: 1.7538x; 1.1475x over previous
#include <cuda_runtime.h>
#include <cuda_bf16.h>
#include <cuda_fp16.h>
#include <cstdint>

#define W_g 200
#define H_g 200
#define NQ 40000
#define Dm 256
#define M_ROWS 40000

// ---------------------------------------------------------------------------
// Device scratch (no allocations allowed)
// ---------------------------------------------------------------------------
__device__ __half g_v[NQ * Dm];       // v = value @ W_v + b_v  (fp16)
__device__ float g_soaw[NQ * 192];    // cols 0..127 so, 128..191 aw (pre-softmax)
__device__ float g_mid[NQ * Dm];      // deform output (fp32)
__device__ __nv_bfloat16 g_wv_hi[256 * 256],  g_wv_lo[256 * 256];     // [n][k]
__device__ __nv_bfloat16 g_wsa_hi[192 * 512], g_wsa_lo[192 * 512];    // W_so|W_aw
__device__ __nv_bfloat16 g_wo_hi[256 * 256],  g_wo_lo[256 * 256];

__device__ __forceinline__ uint32_t smem_u32(const void* p) {
    uint32_t a;
    asm("{ .reg .u64 t; cvta.to.shared.u64 t, %1; cvt.u32.u64 %0, t; }" : "=r"(a) : "l"(p));
    return a;
}
__device__ __forceinline__ void bsplit(float x, __nv_bfloat16& h, __nv_bfloat16& l) {
    h = __float2bfloat16(x);
    l = __float2bfloat16(x - __bfloat162float(h));
}
__device__ __forceinline__ void ldmatrix_x4(uint32_t* r, uint32_t addr) {
    asm volatile("ldmatrix.sync.aligned.m8n8.x4.shared.b16 {%0,%1,%2,%3}, [%4];"
                 : "=r"(r[0]), "=r"(r[1]), "=r"(r[2]), "=r"(r[3]) : "r"(addr));
}
__device__ __forceinline__ void mma_16816(float* c, const uint32_t* a, const uint32_t* b) {
    asm volatile(
        "mma.sync.aligned.m16n8k16.row.col.f32.bf16.bf16.f32 "
        "{%0,%1,%2,%3}, {%4,%5,%6,%7}, {%8,%9}, {%0,%1,%2,%3};"
        : "+f"(c[0]), "+f"(c[1]), "+f"(c[2]), "+f"(c[3])
        : "r"(a[0]), "r"(a[1]), "r"(a[2]), "r"(a[3]), "r"(b[0]), "r"(b[1]));
}
// pack two floats -> bf16x2 (x = lo element in memory)
__device__ __forceinline__ uint32_t pack_bf2(float a, float b) {
    __nv_bfloat162 t = __floats2bfloat162_rn(a, b);
    return *reinterpret_cast<uint32_t*>(&t);
}

// ---------------------------------------------------------------------------
// Split-fp32 GEMM via bf16 mma.sync, conversion fused into the A loader.
// C[m,n] = sum_k A[m,k] * Bt[n,k] + bias(n)
// A fp32 (CONCAT: k<256 -> A, k>=256 -> A+A2, phys row stride 256).
// Bt pre-split bf16 hi/lo [n][k]. Per k-chunk (BK=32) the A tile is split
// in-register to hi/lo smem tiles; 3 MMA passes: hi*Bhi + lo*Bhi + hi*Blo.
// Block 128x128, 256 threads (8 warps 2x4, warp tile 64x32), double buffered.
// ---------------------------------------------------------------------------
template <bool CONCAT, bool HALF_OUT>
__global__ __launch_bounds__(256) void gemm_mma(
    const float* __restrict__ A, const float* __restrict__ A2, int ldA,
    const __nv_bfloat16* __restrict__ Bhi, const __nv_bfloat16* __restrict__ Blo,
    int K, int Nb,
    const float* __restrict__ bias0, const float* __restrict__ bias1, int nsplit,
    void* __restrict__ Cv, int ldC)
{
    extern __shared__ uint8_t smem[];
    constexpr int TP = 128 * 80;        // one tile (128 rows x 80B), bytes
    uint8_t* sAh = smem;                // [2][TP]
    uint8_t* sAl = smem + 2 * TP;
    uint8_t* sBh = smem + 4 * TP;
    uint8_t* sBl = smem + 6 * TP;

    const int tid  = threadIdx.x;
    const int lane = tid & 31;
    const int wid  = tid >> 5;
    const int wr   = wid >> 2;
    const int wc   = wid & 3;
    const int bm   = blockIdx.y * 128;
    const int bn   = blockIdx.x * 128;

    float acc[4][4][4];
    #pragma unroll
    for (int i = 0; i < 4; ++i)
        #pragma unroll
        for (int j = 0; j < 4; ++j)
            #pragma unroll
            for (int k = 0; k < 4; ++k) acc[i][j][k] = 0.f;

    const int nchunk = K >> 5;

    float4 ra[4];
    uint4  rbh[2], rbl[2];

    auto ldg_chunk = [&](int c) {
        const int k0 = c << 5;
        #pragma unroll
        for (int i = 0; i < 4; ++i) {
            const int s = tid + i * 256;
            const int row = s >> 3, g = (s & 7) << 2;       // col in floats
            const int rg = min(bm + row, M_ROWS - 1);
            if (!CONCAT || k0 < 256) {
                ra[i] = *(const float4*)(A + (size_t)rg * ldA + k0 + g);
            } else {
                const int kk = k0 - 256;
                float4 p = *(const float4*)(A  + (size_t)rg * ldA + kk + g);
                float4 q = *(const float4*)(A2 + (size_t)rg * ldA + kk + g);
                ra[i] = make_float4(p.x + q.x, p.y + q.y, p.z + q.z, p.w + q.w);
            }
        }
        #pragma unroll
        for (int i = 0; i < 2; ++i) {
            const int s = tid + i * 256;
            const int row = s >> 2, g = (s & 3) << 3;       // col in bf16 elems
            const int rg = min(bn + row, Nb - 1);
            rbh[i] = *(const uint4*)(Bhi + (size_t)rg * K + k0 + g);
            rbl[i] = *(const uint4*)(Blo + (size_t)rg * K + k0 + g);
        }
    };

    auto sts_chunk = [&](int buf) {
        #pragma unroll
        for (int i = 0; i < 4; ++i) {
            const int s = tid + i * 256;
            const int row = s >> 3, g = s & 7;              // 8B chunk index
            __nv_bfloat16 hx, lx, hy, ly, hz, lz, hw, lw;
            bsplit(ra[i].x, hx, lx); bsplit(ra[i].y, hy, ly);
            bsplit(ra[i].z, hz, lz); bsplit(ra[i].w, hw, lw);
            uint2 hh = make_uint2(pack_bf2(__bfloat162float(hx), __bfloat162float(hy)),
                                  pack_bf2(__bfloat162float(hz), __bfloat162float(hw)));
            uint2 ll = make_uint2(pack_bf2(__bfloat162float(lx), __bfloat162float(ly)),
                                  pack_bf2(__bfloat162float(lz), __bfloat162float(lw)));
            *(uint2*)(sAh + buf * TP + row * 80 + g * 8) = hh;
            *(uint2*)(sAl + buf * TP + row * 80 + g * 8) = ll;
        }
        #pragma unroll
        for (int i = 0; i < 2; ++i) {
            const int s = tid + i * 256;
            const int row = s >> 2, g = s & 3;
            *(uint4*)(sBh + buf * TP + row * 80 + g * 16) = rbh[i];
            *(uint4*)(sBl + buf * TP + row * 80 + g * 16) = rbl[i];
        }
    };

    // lane address components (ldmatrix.x4, non-trans) — validated in R6
    const int a_r = (((lane >> 3) & 1) << 3) + (lane & 7);
    const int a_c = (lane >> 4) << 3;
    const int b_r = ((lane >> 4) << 3) + (lane & 7);
    const int b_c = ((lane >> 3) & 1) << 3;

    ldg_chunk(0);
    sts_chunk(0);
    __syncthreads();

    for (int c = 0; c < nchunk; ++c) {
        const int cur = c & 1;
        if (c + 1 < nchunk) ldg_chunk(c + 1);

        const uint32_t bAh = smem_u32(sAh + cur * TP);
        const uint32_t bAl = smem_u32(sAl + cur * TP);
        const uint32_t bBh = smem_u32(sBh + cur * TP);
        const uint32_t bBl = smem_u32(sBl + cur * TP);

        #pragma unroll
        for (int kk = 0; kk < 32; kk += 16) {
            uint32_t afh[4][4], afl[4][4];
            #pragma unroll
            for (int mc = 0; mc < 4; ++mc) {
                const uint32_t ro = (wr * 64 + mc * 16 + a_r) * 80 + (kk + a_c) * 2;
                ldmatrix_x4(afh[mc], bAh + ro);
                ldmatrix_x4(afl[mc], bAl + ro);
            }
            uint32_t bfh[4][2], bfl[4][2];
            #pragma unroll
            for (int jj = 0; jj < 2; ++jj) {
                const uint32_t ro = (wc * 32 + jj * 16 + b_r) * 80 + (kk + b_c) * 2;
                uint32_t r[4];
                ldmatrix_x4(r, bBh + ro);
                bfh[jj * 2 + 0][0] = r[0]; bfh[jj * 2 + 0][1] = r[1];
                bfh[jj * 2 + 1][0] = r[2]; bfh[jj * 2 + 1][1] = r[3];
                ldmatrix_x4(r, bBl + ro);
                bfl[jj * 2 + 0][0] = r[0]; bfl[jj * 2 + 0][1] = r[1];
                bfl[jj * 2 + 1][0] = r[2]; bfl[jj * 2 + 1][1] = r[3];
            }
            #pragma unroll
            for (int mc = 0; mc < 4; ++mc)
                #pragma unroll
                for (int ncn = 0; ncn < 4; ++ncn) {
                    mma_16816(acc[mc][ncn], afh[mc], bfh[ncn]);
                    mma_16816(acc[mc][ncn], afl[mc], bfh[ncn]);
                    mma_16816(acc[mc][ncn], afh[mc], bfl[ncn]);
                }
        }

        if (c + 1 < nchunk) {
            sts_chunk(1 - cur);
            __syncthreads();
        }
    }

    // ---- epilogue ----
    const int gid = lane >> 2, tig = lane & 3;
    #pragma unroll
    for (int mc = 0; mc < 4; ++mc) {
        #pragma unroll
        for (int ncn = 0; ncn < 4; ++ncn) {
            const int n0 = bn + wc * 32 + ncn * 8 + tig * 2;
            if (n0 >= Nb) continue;
            const float bx = (n0     < nsplit) ? bias0[n0]     : bias1[n0 - nsplit];
            const float by = (n0 + 1 < nsplit) ? bias0[n0 + 1] : bias1[n0 + 1 - nsplit];
            const int m0 = bm + wr * 64 + mc * 16 + gid;
            if (HALF_OUT) {
                __half* C = (__half*)Cv;
                if (m0 < M_ROWS)
                    *(__half2*)&C[(size_t)m0 * ldC + n0] =
                        __floats2half2_rn(acc[mc][ncn][0] + bx, acc[mc][ncn][1] + by);
                if (m0 + 8 < M_ROWS)
                    *(__half2*)&C[(size_t)(m0 + 8) * ldC + n0] =
                        __floats2half2_rn(acc[mc][ncn][2] + bx, acc[mc][ncn][3] + by);
            } else {
                float* C = (float*)Cv;
                if (m0 < M_ROWS)
                    *(float2*)&C[(size_t)m0 * ldC + n0] =
                        make_float2(acc[mc][ncn][0] + bx, acc[mc][ncn][1] + by);
                if (m0 + 8 < M_ROWS)
                    *(float2*)&C[(size_t)(m0 + 8) * ldC + n0] =
                        make_float2(acc[mc][ncn][2] + bx, acc[mc][ncn][3] + by);
            }
        }
    }
}

// ---------------------------------------------------------------------------
// Weight transpose + split:  out[(nOff+n)*ldOut + k] = split(W[k*Ndim + n])
// ---------------------------------------------------------------------------
__global__ void conv_w(const float* __restrict__ W, __nv_bfloat16* __restrict__ hi,
                       __nv_bfloat16* __restrict__ lo, int Kdim, int Ndim, int nOff, int ldOut)
{
    for (int i = blockIdx.x * blockDim.x + threadIdx.x; i < Kdim * Ndim;
         i += gridDim.x * blockDim.x) {
        const int k = i / Ndim, n = i % Ndim;
        __nv_bfloat16 h, l;
        bsplit(W[i], h, l);
        hi[(size_t)(nOff + n) * ldOut + k] = h;
        lo[(size_t)(nOff + n) * ldOut + k] = l;
    }
}

// ---------------------------------------------------------------------------
// Deformable sampling, two-phase, fp16 v.
// Phase 2: warp = head; half-warp = one point of a pair; lane pair = 2 channels
// via __half2; cross-half-warp reduction with shfl_xor(16).
// ---------------------------------------------------------------------------
__global__ __launch_bounds__(256) void deform_kernel(
    const __half* __restrict__ v, const float* __restrict__ soaw,
    const float* __restrict__ ref, float* __restrict__ mid)
{
    __shared__ float4 s_w[64];
    __shared__ int4   s_idx[64];

    const int q   = blockIdx.x;
    const int tid = threadIdx.x;

    if (tid < 64) {
        const int h  = tid >> 3;
        const int qq = (tid >> 2) & 1;
        const int p  = tid & 3;
        const float* srow = soaw + (size_t)q * 192;

        const float rpx = ref[q * 2 + 0];
        const float rpy = ref[q * 2 + 1];

        const float sx = srow[h * 16 + qq * 8 + p * 2 + 0];
        const float sy = srow[h * 16 + qq * 8 + p * 2 + 1];
        float a        = srow[128 + h * 8 + qq * 4 + p];

        float m = fmaxf(a, __shfl_xor_sync(0xffffffffu, a, 1));
        m = fmaxf(m, __shfl_xor_sync(0xffffffffu, m, 2));
        float e = __expf(a - m);
        float s = e + __shfl_xor_sync(0xffffffffu, e, 1);
        s = s + __shfl_xor_sync(0xffffffffu, s, 2);
        const float wt = 0.5f * e / s;

        const float x = fmaf(rpx, (float)W_g, sx) - 0.5f;
        const float y = fmaf(rpy, (float)H_g, sy) - 0.5f;
        const float x0f = floorf(x), y0f = floorf(y);
        const int   x0 = (int)x0f,  y0 = (int)y0f;
        const float wx1 = x - x0f, wx0 = 1.f - wx1;
        const float wy1 = y - y0f, wy0 = 1.f - wy1;

        const bool vx0 = (x0 >= 0) && (x0 < W_g);
        const bool vx1 = (x0 + 1 >= 0) && (x0 + 1 < W_g);
        const bool vy0 = (y0 >= 0) && (y0 < H_g);
        const bool vy1 = (y0 + 1 >= 0) && (y0 + 1 < H_g);
        const int cx0 = min(max(x0, 0),     W_g - 1);
        const int cx1 = min(max(x0 + 1, 0), W_g - 1);
        const int cy0 = min(max(y0, 0),     H_g - 1);
        const int cy1 = min(max(y0 + 1, 0), H_g - 1);

        float4 w;
        w.x = wt * wx0 * wy0 * (float)(vx0 && vy0);
        w.y = wt * wx1 * wy0 * (float)(vx1 && vy0);
        w.z = wt * wx0 * wy1 * (float)(vx0 && vy1);
        w.w = wt * wx1 * wy1 * (float)(vx1 && vy1);

        int4 ix;   // byte offsets; v row = 256 half = 512 B
        ix.x = (cy0 * W_g + cx0) * 512;
        ix.y = (cy0 * W_g + cx1) * 512;
        ix.z = (cy1 * W_g + cx0) * 512;
        ix.w = (cy1 * W_g + cx1) * 512;

        s_w[tid]   = w;
        s_idx[tid] = ix;
    }
    __syncthreads();

    const int h    = tid >> 5;
    const int lane = tid & 31;
    const int sel  = lane >> 4;          // which point of the pair
    const int ch   = (lane & 15) * 2;    // channel pair
    const char* vh = (const char*)v + (size_t)(h * 32 + ch) * 2;

    float2 acc = make_float2(0.f, 0.f);
    #pragma unroll
    for (int i = 0; i < 4; ++i) {
        const int t = h * 8 + i * 2 + sel;
        const float4 w  = s_w[t];
        const int4   ix = s_idx[t];
        float2 f;
        f = __half22float2(*(const __half2*)(vh + ix.x));
        acc.x = fmaf(w.x, f.x, acc.x); acc.y = fmaf(w.x, f.y, acc.y);
        f = __half22float2(*(const __half2*)(vh + ix.y));
        acc.x = fmaf(w.y, f.x, acc.x); acc.y = fmaf(w.y, f.y, acc.y);
        f = __half22float2(*(const __half2*)(vh + ix.z));
        acc.x = fmaf(w.z, f.x, acc.x); acc.y = fmaf(w.z, f.y, acc.y);
        f = __half22float2(*(const __half2*)(vh + ix.w));
        acc.x = fmaf(w.w, f.x, acc.x); acc.y = fmaf(w.w, f.y, acc.y);
    }
    acc.x += __shfl_xor_sync(0xffffffffu, acc.x, 16);
    acc.y += __shfl_xor_sync(0xffffffffu, acc.y, 16);

    if (lane < 16)
        *(float2*)&mid[(size_t)q * Dm + h * 32 + ch] = acc;
}

// ---------------------------------------------------------------------------
extern "C" void kernel_launch(void* const* d_in, const int* in_sizes, int n_in,
                              void* d_out, int out_size)
{
    const float* query     = (const float*)d_in[0];
    const float* query_pos = (const float*)d_in[1];
    const float* refpts    = (const float*)d_in[2];
    const float* W_so      = (const float*)d_in[3];
    const float* b_so      = (const float*)d_in[4];
    const float* W_aw      = (const float*)d_in[5];
    const float* b_aw      = (const float*)d_in[6];
    const float* W_v       = (const float*)d_in[7];
    const float* b_v       = (const float*)d_in[8];
    const float* W_o       = (const float*)d_in[9];
    const float* b_o       = (const float*)d_in[10];
    float* out = (float*)d_out;

    __half* gv;  float *gsoaw, *gmid;
    __nv_bfloat16 *wvh, *wvl, *wsh, *wsl, *woh, *wol;
    cudaGetSymbolAddress((void**)&gv,    g_v);
    cudaGetSymbolAddress((void**)&gsoaw, g_soaw);
    cudaGetSymbolAddress((void**)&gmid,  g_mid);
    cudaGetSymbolAddress((void**)&wvh, g_wv_hi);
    cudaGetSymbolAddress((void**)&wvl, g_wv_lo);
    cudaGetSymbolAddress((void**)&wsh, g_wsa_hi);
    cudaGetSymbolAddress((void**)&wsl, g_wsa_lo);
    cudaGetSymbolAddress((void**)&woh, g_wo_hi);
    cudaGetSymbolAddress((void**)&wol, g_wo_lo);

    constexpr int SMEM = 8 * 128 * 80;   // 81920 B
    cudaFuncSetAttribute(gemm_mma<false, true>,  cudaFuncAttributeMaxDynamicSharedMemorySize, SMEM);
    cudaFuncSetAttribute(gemm_mma<true,  false>, cudaFuncAttributeMaxDynamicSharedMemorySize, SMEM);
    cudaFuncSetAttribute(gemm_mma<false, false>, cudaFuncAttributeMaxDynamicSharedMemorySize, SMEM);

    const int gm = (M_ROWS + 127) / 128;  // 313

    // weight transpose + split (small)
    conv_w<<<256, 256>>>(W_v,  wvh, wvl, 256, 256, 0,   256);
    conv_w<<<256, 256>>>(W_so, wsh, wsl, 512, 128, 0,   512);
    conv_w<<<128, 256>>>(W_aw, wsh, wsl, 512, 64,  128, 512);
    conv_w<<<256, 256>>>(W_o,  woh, wol, 256, 256, 0,   256);

    // G1: v = query @ W_v + b_v  -> fp16
    gemm_mma<false, true><<<dim3(2, gm), 256, SMEM>>>(
        query, nullptr, 256, wvh, wvl, 256, 256, b_v, b_v, 256, gv, 256);
    // G2: soaw = [q | q+pos] @ [W_so | W_aw] + bias   (K=512, Nb=192)
    gemm_mma<true, false><<<dim3(2, gm), 256, SMEM>>>(
        query, query_pos, 256, wsh, wsl, 512, 192, b_so, b_aw, 128, gsoaw, 192);
    // deform (fp16 gathers, fp32 mid)
    deform_kernel<<<NQ, 256>>>(gv, gsoaw, refpts, gmid);
    // G3: out = mid @ W_o + b_o
    gemm_mma<false, false><<<dim3(2, gm), 256, SMEM>>>(
        gmid, nullptr, 256, woh, wol, 256, 256, b_o, b_o, 256, out, 256);
}

// round 8
// speedup vs baseline: 2.6827x; 1.5296x over previous
#include <cuda_runtime.h>
#include <cuda_fp16.h>
#include <cstdint>

#define W_g 200
#define H_g 200
#define NQ 40000
#define Dm 256
#define M_ROWS 40000

// ---------------------------------------------------------------------------
// Device scratch (no allocations allowed)
// ---------------------------------------------------------------------------
__device__ __half g_v[NQ * Dm];       // v = value @ W_v + b_v  (fp16)
__device__ float g_soaw[NQ * 192];    // cols 0..127 so, 128..191 aw (pre-softmax)
__device__ float g_mid[NQ * Dm];      // deform output (fp32)
__device__ __half g_wv[256 * 256];    // W_v  transposed [n][k], fp16
__device__ __half g_wsa[192 * 512];   // [W_so | W_aw] transposed [n][k], fp16
__device__ __half g_wo[256 * 256];    // W_o  transposed [n][k], fp16

__device__ __forceinline__ uint32_t smem_u32(const void* p) {
    uint32_t a;
    asm("{ .reg .u64 t; cvta.to.shared.u64 t, %1; cvt.u32.u64 %0, t; }" : "=r"(a) : "l"(p));
    return a;
}
__device__ __forceinline__ void ldmatrix_x4(uint32_t* r, uint32_t addr) {
    asm volatile("ldmatrix.sync.aligned.m8n8.x4.shared.b16 {%0,%1,%2,%3}, [%4];"
                 : "=r"(r[0]), "=r"(r[1]), "=r"(r[2]), "=r"(r[3]) : "r"(addr));
}
__device__ __forceinline__ void mma_16816(float* c, const uint32_t* a, const uint32_t* b) {
    asm volatile(
        "mma.sync.aligned.m16n8k16.row.col.f32.f16.f16.f32 "
        "{%0,%1,%2,%3}, {%4,%5,%6,%7}, {%8,%9}, {%0,%1,%2,%3};"
        : "+f"(c[0]), "+f"(c[1]), "+f"(c[2]), "+f"(c[3])
        : "r"(a[0]), "r"(a[1]), "r"(a[2]), "r"(a[3]), "r"(b[0]), "r"(b[1]));
}
// fp16 hi/lo split packed as half2 pairs
__device__ __forceinline__ void hsplit2(float x, float y, uint32_t& hi, uint32_t& lo) {
    __half hx = __float2half(x), hy = __float2half(y);
    __half lx = __float2half(x - __half2float(hx));
    __half ly = __float2half(y - __half2float(hy));
    __half2 h2 = __halves2half2(hx, hy);
    __half2 l2 = __halves2half2(lx, ly);
    hi = *reinterpret_cast<uint32_t*>(&h2);
    lo = *reinterpret_cast<uint32_t*>(&l2);
}

// ---------------------------------------------------------------------------
// Split-fp32 GEMM via fp16 mma.sync, 2 passes (Ahi*B + Alo*B), fused A split.
// C[m,n] = sum_k A[m,k] * Bt[n,k] + bias(n)
// A fp32 (CONCAT: k<256 -> A, k>=256 -> A+A2, phys row stride 256).
// Bt fp16 [n][k]. Block 128x128, BK=32, 256 threads (8 warps 2x4,
// warp tile 64x32), double-buffered smem, rows padded to 80 B.
// ---------------------------------------------------------------------------
template <bool CONCAT, bool HALF_OUT>
__global__ __launch_bounds__(256) void gemm_mma(
    const float* __restrict__ A, const float* __restrict__ A2, int ldA,
    const __half* __restrict__ B, int K, int Nb,
    const float* __restrict__ bias0, const float* __restrict__ bias1, int nsplit,
    void* __restrict__ Cv, int ldC)
{
    extern __shared__ uint8_t smem[];
    constexpr int TP = 128 * 80;
    uint8_t* sAh = smem;                // [2][TP]
    uint8_t* sAl = smem + 2 * TP;
    uint8_t* sB  = smem + 4 * TP;

    const int tid  = threadIdx.x;
    const int lane = tid & 31;
    const int wid  = tid >> 5;
    const int wr   = wid >> 2;
    const int wc   = wid & 3;
    const int bm   = blockIdx.y * 128;
    const int bn   = blockIdx.x * 128;

    float acc[4][4][4];
    #pragma unroll
    for (int i = 0; i < 4; ++i)
        #pragma unroll
        for (int j = 0; j < 4; ++j)
            #pragma unroll
            for (int k = 0; k < 4; ++k) acc[i][j][k] = 0.f;

    const int nchunk = K >> 5;

    float4 ra[4];
    uint4  rb[2];

    auto ldg_chunk = [&](int c) {
        const int k0 = c << 5;
        #pragma unroll
        for (int i = 0; i < 4; ++i) {
            const int s = tid + i * 256;
            const int row = s >> 3, g = (s & 7) << 2;
            const int rg = min(bm + row, M_ROWS - 1);
            if (!CONCAT || k0 < 256) {
                ra[i] = *(const float4*)(A + (size_t)rg * ldA + k0 + g);
            } else {
                const int kk = k0 - 256;
                float4 p = *(const float4*)(A  + (size_t)rg * ldA + kk + g);
                float4 q = *(const float4*)(A2 + (size_t)rg * ldA + kk + g);
                ra[i] = make_float4(p.x + q.x, p.y + q.y, p.z + q.z, p.w + q.w);
            }
        }
        #pragma unroll
        for (int i = 0; i < 2; ++i) {
            const int s = tid + i * 256;
            const int row = s >> 2, g = (s & 3) << 3;
            const int rg = min(bn + row, Nb - 1);
            rb[i] = *(const uint4*)(B + (size_t)rg * K + k0 + g);
        }
    };

    auto sts_chunk = [&](int buf) {
        #pragma unroll
        for (int i = 0; i < 4; ++i) {
            const int s = tid + i * 256;
            const int row = s >> 3, g = s & 7;
            uint2 hh, ll;
            hsplit2(ra[i].x, ra[i].y, hh.x, ll.x);
            hsplit2(ra[i].z, ra[i].w, hh.y, ll.y);
            *(uint2*)(sAh + buf * TP + row * 80 + g * 8) = hh;
            *(uint2*)(sAl + buf * TP + row * 80 + g * 8) = ll;
        }
        #pragma unroll
        for (int i = 0; i < 2; ++i) {
            const int s = tid + i * 256;
            const int row = s >> 2, g = s & 3;
            *(uint4*)(sB + buf * TP + row * 80 + g * 16) = rb[i];
        }
    };

    // lane address components (ldmatrix.x4, non-trans) — validated in R6/R7
    const int a_r = (((lane >> 3) & 1) << 3) + (lane & 7);
    const int a_c = (lane >> 4) << 3;
    const int b_r = ((lane >> 4) << 3) + (lane & 7);
    const int b_c = ((lane >> 3) & 1) << 3;

    ldg_chunk(0);
    sts_chunk(0);
    __syncthreads();

    for (int c = 0; c < nchunk; ++c) {
        const int cur = c & 1;
        if (c + 1 < nchunk) ldg_chunk(c + 1);

        const uint32_t bAh = smem_u32(sAh + cur * TP);
        const uint32_t bAl = smem_u32(sAl + cur * TP);
        const uint32_t bB  = smem_u32(sB  + cur * TP);

        #pragma unroll
        for (int kk = 0; kk < 32; kk += 16) {
            uint32_t afh[4][4], afl[4][4];
            #pragma unroll
            for (int mc = 0; mc < 4; ++mc) {
                const uint32_t ro = (wr * 64 + mc * 16 + a_r) * 80 + (kk + a_c) * 2;
                ldmatrix_x4(afh[mc], bAh + ro);
                ldmatrix_x4(afl[mc], bAl + ro);
            }
            uint32_t bf[4][2];
            #pragma unroll
            for (int jj = 0; jj < 2; ++jj) {
                const uint32_t ro = (wc * 32 + jj * 16 + b_r) * 80 + (kk + b_c) * 2;
                uint32_t r[4];
                ldmatrix_x4(r, bB + ro);
                bf[jj * 2 + 0][0] = r[0]; bf[jj * 2 + 0][1] = r[1];
                bf[jj * 2 + 1][0] = r[2]; bf[jj * 2 + 1][1] = r[3];
            }
            #pragma unroll
            for (int mc = 0; mc < 4; ++mc)
                #pragma unroll
                for (int ncn = 0; ncn < 4; ++ncn) {
                    mma_16816(acc[mc][ncn], afh[mc], bf[ncn]);
                    mma_16816(acc[mc][ncn], afl[mc], bf[ncn]);
                }
        }

        if (c + 1 < nchunk) {
            sts_chunk(1 - cur);
            __syncthreads();
        }
    }

    // ---- epilogue ----
    const int gid = lane >> 2, tig = lane & 3;
    #pragma unroll
    for (int mc = 0; mc < 4; ++mc) {
        #pragma unroll
        for (int ncn = 0; ncn < 4; ++ncn) {
            const int n0 = bn + wc * 32 + ncn * 8 + tig * 2;
            if (n0 >= Nb) continue;
            const float bx = (n0     < nsplit) ? bias0[n0]     : bias1[n0 - nsplit];
            const float by = (n0 + 1 < nsplit) ? bias0[n0 + 1] : bias1[n0 + 1 - nsplit];
            const int m0 = bm + wr * 64 + mc * 16 + gid;
            if (HALF_OUT) {
                __half* C = (__half*)Cv;
                if (m0 < M_ROWS)
                    *(__half2*)&C[(size_t)m0 * ldC + n0] =
                        __floats2half2_rn(acc[mc][ncn][0] + bx, acc[mc][ncn][1] + by);
                if (m0 + 8 < M_ROWS)
                    *(__half2*)&C[(size_t)(m0 + 8) * ldC + n0] =
                        __floats2half2_rn(acc[mc][ncn][2] + bx, acc[mc][ncn][3] + by);
            } else {
                float* C = (float*)Cv;
                if (m0 < M_ROWS)
                    *(float2*)&C[(size_t)m0 * ldC + n0] =
                        make_float2(acc[mc][ncn][0] + bx, acc[mc][ncn][1] + by);
                if (m0 + 8 < M_ROWS)
                    *(float2*)&C[(size_t)(m0 + 8) * ldC + n0] =
                        make_float2(acc[mc][ncn][2] + bx, acc[mc][ncn][3] + by);
            }
        }
    }
}

// ---------------------------------------------------------------------------
// All weight transposes in ONE kernel: W[k][n] fp32 -> out[n][k] fp16.
// Segments: W_v(256x256->g_wv), W_so(512x128->g_wsa rows 0..127),
//           W_aw(512x64->g_wsa rows 128..191), W_o(256x256->g_wo).
// ---------------------------------------------------------------------------
__global__ void conv_w_all(const float* __restrict__ Wv, const float* __restrict__ Wso,
                           const float* __restrict__ Waw, const float* __restrict__ Wo)
{
    const int total = 65536 + 65536 + 32768 + 65536;  // 229376
    for (int i = blockIdx.x * blockDim.x + threadIdx.x; i < total;
         i += gridDim.x * blockDim.x) {
        if (i < 65536) {
            const int k = i >> 8, n = i & 255;
            g_wv[n * 256 + k] = __float2half(Wv[i]);
        } else if (i < 131072) {
            const int j = i - 65536;
            const int k = j >> 7, n = j & 127;
            g_wsa[n * 512 + k] = __float2half(Wso[j]);
        } else if (i < 163840) {
            const int j = i - 131072;
            const int k = j >> 6, n = j & 63;
            g_wsa[(128 + n) * 512 + k] = __float2half(Waw[j]);
        } else {
            const int j = i - 163840;
            const int k = j >> 8, n = j & 255;
            g_wo[n * 256 + k] = __float2half(Wo[j]);
        }
    }
}

// ---------------------------------------------------------------------------
// Deformable sampling, two-phase, fp16 v (unchanged from R7).
// ---------------------------------------------------------------------------
__global__ __launch_bounds__(256) void deform_kernel(
    const __half* __restrict__ v, const float* __restrict__ soaw,
    const float* __restrict__ ref, float* __restrict__ mid)
{
    __shared__ float4 s_w[64];
    __shared__ int4   s_idx[64];

    const int q   = blockIdx.x;
    const int tid = threadIdx.x;

    if (tid < 64) {
        const int h  = tid >> 3;
        const int qq = (tid >> 2) & 1;
        const int p  = tid & 3;
        const float* srow = soaw + (size_t)q * 192;

        const float rpx = ref[q * 2 + 0];
        const float rpy = ref[q * 2 + 1];

        const float sx = srow[h * 16 + qq * 8 + p * 2 + 0];
        const float sy = srow[h * 16 + qq * 8 + p * 2 + 1];
        float a        = srow[128 + h * 8 + qq * 4 + p];

        float m = fmaxf(a, __shfl_xor_sync(0xffffffffu, a, 1));
        m = fmaxf(m, __shfl_xor_sync(0xffffffffu, m, 2));
        float e = __expf(a - m);
        float s = e + __shfl_xor_sync(0xffffffffu, e, 1);
        s = s + __shfl_xor_sync(0xffffffffu, s, 2);
        const float wt = 0.5f * e / s;

        const float x = fmaf(rpx, (float)W_g, sx) - 0.5f;
        const float y = fmaf(rpy, (float)H_g, sy) - 0.5f;
        const float x0f = floorf(x), y0f = floorf(y);
        const int   x0 = (int)x0f,  y0 = (int)y0f;
        const float wx1 = x - x0f, wx0 = 1.f - wx1;
        const float wy1 = y - y0f, wy0 = 1.f - wy1;

        const bool vx0 = (x0 >= 0) && (x0 < W_g);
        const bool vx1 = (x0 + 1 >= 0) && (x0 + 1 < W_g);
        const bool vy0 = (y0 >= 0) && (y0 < H_g);
        const bool vy1 = (y0 + 1 >= 0) && (y0 + 1 < H_g);
        const int cx0 = min(max(x0, 0),     W_g - 1);
        const int cx1 = min(max(x0 + 1, 0), W_g - 1);
        const int cy0 = min(max(y0, 0),     H_g - 1);
        const int cy1 = min(max(y0 + 1, 0), H_g - 1);

        float4 w;
        w.x = wt * wx0 * wy0 * (float)(vx0 && vy0);
        w.y = wt * wx1 * wy0 * (float)(vx1 && vy0);
        w.z = wt * wx0 * wy1 * (float)(vx0 && vy1);
        w.w = wt * wx1 * wy1 * (float)(vx1 && vy1);

        int4 ix;   // byte offsets; v row = 256 half = 512 B
        ix.x = (cy0 * W_g + cx0) * 512;
        ix.y = (cy0 * W_g + cx1) * 512;
        ix.z = (cy1 * W_g + cx0) * 512;
        ix.w = (cy1 * W_g + cx1) * 512;

        s_w[tid]   = w;
        s_idx[tid] = ix;
    }
    __syncthreads();

    const int h    = tid >> 5;
    const int lane = tid & 31;
    const int sel  = lane >> 4;
    const int ch   = (lane & 15) * 2;
    const char* vh = (const char*)v + (size_t)(h * 32 + ch) * 2;

    float2 acc = make_float2(0.f, 0.f);
    #pragma unroll
    for (int i = 0; i < 4; ++i) {
        const int t = h * 8 + i * 2 + sel;
        const float4 w  = s_w[t];
        const int4   ix = s_idx[t];
        float2 f;
        f = __half22float2(*(const __half2*)(vh + ix.x));
        acc.x = fmaf(w.x, f.x, acc.x); acc.y = fmaf(w.x, f.y, acc.y);
        f = __half22float2(*(const __half2*)(vh + ix.y));
        acc.x = fmaf(w.y, f.x, acc.x); acc.y = fmaf(w.y, f.y, acc.y);
        f = __half22float2(*(const __half2*)(vh + ix.z));
        acc.x = fmaf(w.z, f.x, acc.x); acc.y = fmaf(w.z, f.y, acc.y);
        f = __half22float2(*(const __half2*)(vh + ix.w));
        acc.x = fmaf(w.w, f.x, acc.x); acc.y = fmaf(w.w, f.y, acc.y);
    }
    acc.x += __shfl_xor_sync(0xffffffffu, acc.x, 16);
    acc.y += __shfl_xor_sync(0xffffffffu, acc.y, 16);

    if (lane < 16)
        *(float2*)&mid[(size_t)q * Dm + h * 32 + ch] = acc;
}

// ---------------------------------------------------------------------------
extern "C" void kernel_launch(void* const* d_in, const int* in_sizes, int n_in,
                              void* d_out, int out_size)
{
    const float* query     = (const float*)d_in[0];
    const float* query_pos = (const float*)d_in[1];
    const float* refpts    = (const float*)d_in[2];
    const float* W_so      = (const float*)d_in[3];
    const float* b_so      = (const float*)d_in[4];
    const float* W_aw      = (const float*)d_in[5];
    const float* b_aw      = (const float*)d_in[6];
    const float* W_v       = (const float*)d_in[7];
    const float* b_v       = (const float*)d_in[8];
    const float* W_o       = (const float*)d_in[9];
    const float* b_o       = (const float*)d_in[10];
    float* out = (float*)d_out;

    __half* gv;  float *gsoaw, *gmid;
    __half *wv, *wsa, *wo;
    cudaGetSymbolAddress((void**)&gv,    g_v);
    cudaGetSymbolAddress((void**)&gsoaw, g_soaw);
    cudaGetSymbolAddress((void**)&gmid,  g_mid);
    cudaGetSymbolAddress((void**)&wv,  g_wv);
    cudaGetSymbolAddress((void**)&wsa, g_wsa);
    cudaGetSymbolAddress((void**)&wo,  g_wo);

    constexpr int SMEM = 6 * 128 * 80;   // 61440 B
    cudaFuncSetAttribute(gemm_mma<false, true>,  cudaFuncAttributeMaxDynamicSharedMemorySize, SMEM);
    cudaFuncSetAttribute(gemm_mma<true,  false>, cudaFuncAttributeMaxDynamicSharedMemorySize, SMEM);
    cudaFuncSetAttribute(gemm_mma<false, false>, cudaFuncAttributeMaxDynamicSharedMemorySize, SMEM);

    const int gm = (M_ROWS + 127) / 128;  // 313

    // all weight transposes in one launch
    conv_w_all<<<448, 512>>>(W_v, W_so, W_aw, W_o);

    // G1: v = query @ W_v + b_v  -> fp16
    gemm_mma<false, true><<<dim3(2, gm), 256, SMEM>>>(
        query, nullptr, 256, wv, 256, 256, b_v, b_v, 256, gv, 256);
    // G2: soaw = [q | q+pos] @ [W_so | W_aw] + bias   (K=512, Nb=192)
    gemm_mma<true, false><<<dim3(2, gm), 256, SMEM>>>(
        query, query_pos, 256, wsa, 512, 192, b_so, b_aw, 128, gsoaw, 192);
    // deform (fp16 gathers, fp32 mid)
    deform_kernel<<<NQ, 256>>>(gv, gsoaw, refpts, gmid);
    // G3: out = mid @ W_o + b_o
    gemm_mma<false, false><<<dim3(2, gm), 256, SMEM>>>(
        gmid, nullptr, 256, wo, 256, 256, b_o, b_o, 256, out, 256);
}

// round 9
// speedup vs baseline: 3.4037x; 1.2688x over previous
#include <cuda_runtime.h>
#include <cuda_fp16.h>
#include <cstdint>

#define W_g 200
#define H_g 200
#define NQ 40000
#define Dm 256
#define M_ROWS 40000

// ---------------------------------------------------------------------------
// Device scratch (no allocations allowed)
// ---------------------------------------------------------------------------
__device__ __half g_v[NQ * Dm];       // v = value @ W_v + b_v  (fp16)
__device__ float g_soaw[NQ * 192];    // cols 0..127 so, 128..191 aw (pre-softmax)
__device__ float g_mid[NQ * Dm];      // deform output (fp32)
__device__ __half g_wv[256 * 256];    // W_v  transposed [n][k], fp16
__device__ __half g_wsa[192 * 512];   // [W_so | W_aw] transposed [n][k], fp16
__device__ __half g_wo[256 * 256];    // W_o  transposed [n][k], fp16

__device__ __forceinline__ uint32_t smem_u32(const void* p) {
    uint32_t a;
    asm("{ .reg .u64 t; cvta.to.shared.u64 t, %1; cvt.u32.u64 %0, t; }" : "=r"(a) : "l"(p));
    return a;
}
__device__ __forceinline__ void ldmatrix_x4(uint32_t* r, uint32_t addr) {
    asm volatile("ldmatrix.sync.aligned.m8n8.x4.shared.b16 {%0,%1,%2,%3}, [%4];"
                 : "=r"(r[0]), "=r"(r[1]), "=r"(r[2]), "=r"(r[3]) : "r"(addr));
}
__device__ __forceinline__ void mma_16816(float* c, const uint32_t* a, const uint32_t* b) {
    asm volatile(
        "mma.sync.aligned.m16n8k16.row.col.f32.f16.f16.f32 "
        "{%0,%1,%2,%3}, {%4,%5,%6,%7}, {%8,%9}, {%0,%1,%2,%3};"
        : "+f"(c[0]), "+f"(c[1]), "+f"(c[2]), "+f"(c[3])
        : "r"(a[0]), "r"(a[1]), "r"(a[2]), "r"(a[3]), "r"(b[0]), "r"(b[1]));
}
__device__ __forceinline__ uint32_t pack_h2(float x, float y) {
    __half2 t = __floats2half2_rn(x, y);
    return *reinterpret_cast<uint32_t*>(&t);
}

// ---------------------------------------------------------------------------
// fp16 GEMM tile (single pass). C[m,n] = sum_k A[m,k]*Bt[n,k] + bias(n).
// A fp32 converted to fp16 in the loader (CONCAT: k>=256 -> A+A2).
// Block tile 128x128, BK=32, 8 warps (2x4), warp tile 64x32, double buffer.
// smem rows padded to 80 B. sA/sB each hold 2 buffers of 10240 B.
// ---------------------------------------------------------------------------
template <bool CONCAT, bool HALF_OUT>
__device__ __forceinline__ void tile_gemm(
    const float* __restrict__ A, const float* __restrict__ A2, int ldA,
    const __half* __restrict__ B, int K, int Nb,
    const float* __restrict__ bias0, const float* __restrict__ bias1, int nsplit,
    void* __restrict__ Cv, int ldC, int bm, int bn,
    uint8_t* sA, uint8_t* sB)
{
    constexpr int TP = 128 * 80;  // 10240 B per buffer

    const int tid  = threadIdx.x;
    const int lane = tid & 31;
    const int wid  = tid >> 5;
    const int wr   = wid >> 2;
    const int wc   = wid & 3;

    float acc[4][4][4];
    #pragma unroll
    for (int i = 0; i < 4; ++i)
        #pragma unroll
        for (int j = 0; j < 4; ++j)
            #pragma unroll
            for (int k = 0; k < 4; ++k) acc[i][j][k] = 0.f;

    const int nchunk = K >> 5;

    float4 ra[4];
    uint4  rb[2];

    auto ldg_chunk = [&](int c) {
        const int k0 = c << 5;
        #pragma unroll
        for (int i = 0; i < 4; ++i) {
            const int s = tid + i * 256;
            const int row = s >> 3, g = (s & 7) << 2;       // float col
            const int rg = min(bm + row, M_ROWS - 1);
            if (!CONCAT || k0 < 256) {
                ra[i] = *(const float4*)(A + (size_t)rg * ldA + k0 + g);
            } else {
                const int kk = k0 - 256;
                float4 p = *(const float4*)(A  + (size_t)rg * ldA + kk + g);
                float4 q = *(const float4*)(A2 + (size_t)rg * ldA + kk + g);
                ra[i] = make_float4(p.x + q.x, p.y + q.y, p.z + q.z, p.w + q.w);
            }
        }
        #pragma unroll
        for (int i = 0; i < 2; ++i) {
            const int s = tid + i * 256;
            const int row = s >> 2, g = s & 3;              // 16B unit
            const int rg = min(bn + row, Nb - 1);
            rb[i] = *(const uint4*)(B + (size_t)rg * K + k0 + g * 8);
        }
    };

    auto sts_chunk = [&](int buf) {
        #pragma unroll
        for (int i = 0; i < 4; ++i) {
            const int s = tid + i * 256;
            const int row = s >> 3, g = (s & 7) << 2;       // half col (same idx)
            uint2 hh;
            hh.x = pack_h2(ra[i].x, ra[i].y);
            hh.y = pack_h2(ra[i].z, ra[i].w);
            *(uint2*)(sA + buf * TP + row * 80 + g * 2) = hh;
        }
        #pragma unroll
        for (int i = 0; i < 2; ++i) {
            const int s = tid + i * 256;
            const int row = s >> 2, g = s & 3;
            *(uint4*)(sB + buf * TP + row * 80 + g * 16) = rb[i];
        }
    };

    // ldmatrix lane addressing (non-trans, validated R6-R8)
    const int a_r = (((lane >> 3) & 1) << 3) + (lane & 7);
    const int a_c = (lane >> 4) << 3;
    const int b_r = ((lane >> 4) << 3) + (lane & 7);
    const int b_c = ((lane >> 3) & 1) << 3;

    ldg_chunk(0);
    sts_chunk(0);
    __syncthreads();

    for (int c = 0; c < nchunk; ++c) {
        const int cur = c & 1;
        if (c + 1 < nchunk) ldg_chunk(c + 1);

        const uint32_t bA = smem_u32(sA + cur * TP);
        const uint32_t bB = smem_u32(sB + cur * TP);

        #pragma unroll
        for (int kk = 0; kk < 32; kk += 16) {
            uint32_t af[4][4];
            #pragma unroll
            for (int mc = 0; mc < 4; ++mc)
                ldmatrix_x4(af[mc], bA + (wr * 64 + mc * 16 + a_r) * 80 + (kk + a_c) * 2);
            uint32_t bf[4][2];
            #pragma unroll
            for (int jj = 0; jj < 2; ++jj) {
                uint32_t r[4];
                ldmatrix_x4(r, bB + (wc * 32 + jj * 16 + b_r) * 80 + (kk + b_c) * 2);
                bf[jj * 2 + 0][0] = r[0]; bf[jj * 2 + 0][1] = r[1];
                bf[jj * 2 + 1][0] = r[2]; bf[jj * 2 + 1][1] = r[3];
            }
            #pragma unroll
            for (int mc = 0; mc < 4; ++mc)
                #pragma unroll
                for (int ncn = 0; ncn < 4; ++ncn)
                    mma_16816(acc[mc][ncn], af[mc], bf[ncn]);
        }

        if (c + 1 < nchunk) {
            sts_chunk(1 - cur);
            __syncthreads();
        }
    }

    // ---- epilogue ----
    const int gid = lane >> 2, tig = lane & 3;
    #pragma unroll
    for (int mc = 0; mc < 4; ++mc) {
        #pragma unroll
        for (int ncn = 0; ncn < 4; ++ncn) {
            const int n0 = bn + wc * 32 + ncn * 8 + tig * 2;
            if (n0 >= Nb) continue;
            const float bx = (n0     < nsplit) ? bias0[n0]     : bias1[n0 - nsplit];
            const float by = (n0 + 1 < nsplit) ? bias0[n0 + 1] : bias1[n0 + 1 - nsplit];
            const int m0 = bm + wr * 64 + mc * 16 + gid;
            if (HALF_OUT) {
                __half* C = (__half*)Cv;
                if (m0 < M_ROWS)
                    *(__half2*)&C[(size_t)m0 * ldC + n0] =
                        __floats2half2_rn(acc[mc][ncn][0] + bx, acc[mc][ncn][1] + by);
                if (m0 + 8 < M_ROWS)
                    *(__half2*)&C[(size_t)(m0 + 8) * ldC + n0] =
                        __floats2half2_rn(acc[mc][ncn][2] + bx, acc[mc][ncn][3] + by);
            } else {
                float* C = (float*)Cv;
                if (m0 < M_ROWS)
                    *(float2*)&C[(size_t)m0 * ldC + n0] =
                        make_float2(acc[mc][ncn][0] + bx, acc[mc][ncn][1] + by);
                if (m0 + 8 < M_ROWS)
                    *(float2*)&C[(size_t)(m0 + 8) * ldC + n0] =
                        make_float2(acc[mc][ncn][2] + bx, acc[mc][ncn][3] + by);
            }
        }
    }
}

// ---------------------------------------------------------------------------
// Fused G1+G2 kernel: bx<2 -> v GEMM (K=256, fp16 out), bx>=2 -> soaw GEMM
// (K=512 concat, fp32 out). One grid = tails amortized across both GEMMs.
// ---------------------------------------------------------------------------
__global__ __launch_bounds__(256) void gemm_g12(
    const float* __restrict__ query, const float* __restrict__ query_pos,
    const __half* __restrict__ wv, const __half* __restrict__ wsa,
    const float* __restrict__ b_v, const float* __restrict__ b_so,
    const float* __restrict__ b_aw,
    __half* __restrict__ gv, float* __restrict__ gsoaw)
{
    __shared__ __align__(16) uint8_t sA[2 * 128 * 80];
    __shared__ __align__(16) uint8_t sB[2 * 128 * 80];

    const int bx = blockIdx.x;
    const int bm = blockIdx.y * 128;
    if (bx < 2) {
        tile_gemm<false, true>(query, nullptr, 256, wv, 256, 256,
                               b_v, b_v, 256, gv, 256, bm, bx * 128, sA, sB);
    } else {
        tile_gemm<true, false>(query, query_pos, 256, wsa, 512, 192,
                               b_so, b_aw, 128, gsoaw, 192, bm, (bx - 2) * 128, sA, sB);
    }
}

// G3: out = mid @ W_o + b_o
__global__ __launch_bounds__(256) void gemm_g3(
    const float* __restrict__ mid, const __half* __restrict__ wo,
    const float* __restrict__ b_o, float* __restrict__ out)
{
    __shared__ __align__(16) uint8_t sA[2 * 128 * 80];
    __shared__ __align__(16) uint8_t sB[2 * 128 * 80];
    tile_gemm<false, false>(mid, nullptr, 256, wo, 256, 256,
                            b_o, b_o, 256, out, 256,
                            blockIdx.y * 128, blockIdx.x * 128, sA, sB);
}

// ---------------------------------------------------------------------------
// All weight transposes in ONE kernel: W[k][n] fp32 -> out[n][k] fp16.
// ---------------------------------------------------------------------------
__global__ void conv_w_all(const float* __restrict__ Wv, const float* __restrict__ Wso,
                           const float* __restrict__ Waw, const float* __restrict__ Wo)
{
    const int total = 65536 + 65536 + 32768 + 65536;
    for (int i = blockIdx.x * blockDim.x + threadIdx.x; i < total;
         i += gridDim.x * blockDim.x) {
        if (i < 65536) {
            const int k = i >> 8, n = i & 255;
            g_wv[n * 256 + k] = __float2half(Wv[i]);
        } else if (i < 131072) {
            const int j = i - 65536;
            const int k = j >> 7, n = j & 127;
            g_wsa[n * 512 + k] = __float2half(Wso[j]);
        } else if (i < 163840) {
            const int j = i - 131072;
            const int k = j >> 6, n = j & 63;
            g_wsa[(128 + n) * 512 + k] = __float2half(Waw[j]);
        } else {
            const int j = i - 163840;
            const int k = j >> 8, n = j & 255;
            g_wo[n * 256 + k] = __float2half(Wo[j]);
        }
    }
}

// ---------------------------------------------------------------------------
// Deformable sampling, two-phase, fp16 v (unchanged from R8).
// ---------------------------------------------------------------------------
__global__ __launch_bounds__(256) void deform_kernel(
    const __half* __restrict__ v, const float* __restrict__ soaw,
    const float* __restrict__ ref, float* __restrict__ mid)
{
    __shared__ float4 s_w[64];
    __shared__ int4   s_idx[64];

    const int q   = blockIdx.x;
    const int tid = threadIdx.x;

    if (tid < 64) {
        const int h  = tid >> 3;
        const int qq = (tid >> 2) & 1;
        const int p  = tid & 3;
        const float* srow = soaw + (size_t)q * 192;

        const float rpx = ref[q * 2 + 0];
        const float rpy = ref[q * 2 + 1];

        const float sx = srow[h * 16 + qq * 8 + p * 2 + 0];
        const float sy = srow[h * 16 + qq * 8 + p * 2 + 1];
        float a        = srow[128 + h * 8 + qq * 4 + p];

        float m = fmaxf(a, __shfl_xor_sync(0xffffffffu, a, 1));
        m = fmaxf(m, __shfl_xor_sync(0xffffffffu, m, 2));
        float e = __expf(a - m);
        float s = e + __shfl_xor_sync(0xffffffffu, e, 1);
        s = s + __shfl_xor_sync(0xffffffffu, s, 2);
        const float wt = 0.5f * e / s;

        const float x = fmaf(rpx, (float)W_g, sx) - 0.5f;
        const float y = fmaf(rpy, (float)H_g, sy) - 0.5f;
        const float x0f = floorf(x), y0f = floorf(y);
        const int   x0 = (int)x0f,  y0 = (int)y0f;
        const float wx1 = x - x0f, wx0 = 1.f - wx1;
        const float wy1 = y - y0f, wy0 = 1.f - wy1;

        const bool vx0 = (x0 >= 0) && (x0 < W_g);
        const bool vx1 = (x0 + 1 >= 0) && (x0 + 1 < W_g);
        const bool vy0 = (y0 >= 0) && (y0 < H_g);
        const bool vy1 = (y0 + 1 >= 0) && (y0 + 1 < H_g);
        const int cx0 = min(max(x0, 0),     W_g - 1);
        const int cx1 = min(max(x0 + 1, 0), W_g - 1);
        const int cy0 = min(max(y0, 0),     H_g - 1);
        const int cy1 = min(max(y0 + 1, 0), H_g - 1);

        float4 w;
        w.x = wt * wx0 * wy0 * (float)(vx0 && vy0);
        w.y = wt * wx1 * wy0 * (float)(vx1 && vy0);
        w.z = wt * wx0 * wy1 * (float)(vx0 && vy1);
        w.w = wt * wx1 * wy1 * (float)(vx1 && vy1);

        int4 ix;   // byte offsets; v row = 256 half = 512 B
        ix.x = (cy0 * W_g + cx0) * 512;
        ix.y = (cy0 * W_g + cx1) * 512;
        ix.z = (cy1 * W_g + cx0) * 512;
        ix.w = (cy1 * W_g + cx1) * 512;

        s_w[tid]   = w;
        s_idx[tid] = ix;
    }
    __syncthreads();

    const int h    = tid >> 5;
    const int lane = tid & 31;
    const int sel  = lane >> 4;
    const int ch   = (lane & 15) * 2;
    const char* vh = (const char*)v + (size_t)(h * 32 + ch) * 2;

    float2 acc = make_float2(0.f, 0.f);
    #pragma unroll
    for (int i = 0; i < 4; ++i) {
        const int t = h * 8 + i * 2 + sel;
        const float4 w  = s_w[t];
        const int4   ix = s_idx[t];
        float2 f;
        f = __half22float2(*(const __half2*)(vh + ix.x));
        acc.x = fmaf(w.x, f.x, acc.x); acc.y = fmaf(w.x, f.y, acc.y);
        f = __half22float2(*(const __half2*)(vh + ix.y));
        acc.x = fmaf(w.y, f.x, acc.x); acc.y = fmaf(w.y, f.y, acc.y);
        f = __half22float2(*(const __half2*)(vh + ix.z));
        acc.x = fmaf(w.z, f.x, acc.x); acc.y = fmaf(w.z, f.y, acc.y);
        f = __half22float2(*(const __half2*)(vh + ix.w));
        acc.x = fmaf(w.w, f.x, acc.x); acc.y = fmaf(w.w, f.y, acc.y);
    }
    acc.x += __shfl_xor_sync(0xffffffffu, acc.x, 16);
    acc.y += __shfl_xor_sync(0xffffffffu, acc.y, 16);

    if (lane < 16)
        *(float2*)&mid[(size_t)q * Dm + h * 32 + ch] = acc;
}

// ---------------------------------------------------------------------------
extern "C" void kernel_launch(void* const* d_in, const int* in_sizes, int n_in,
                              void* d_out, int out_size)
{
    const float* query     = (const float*)d_in[0];
    const float* query_pos = (const float*)d_in[1];
    const float* refpts    = (const float*)d_in[2];
    const float* W_so      = (const float*)d_in[3];
    const float* b_so      = (const float*)d_in[4];
    const float* W_aw      = (const float*)d_in[5];
    const float* b_aw      = (const float*)d_in[6];
    const float* W_v       = (const float*)d_in[7];
    const float* b_v       = (const float*)d_in[8];
    const float* W_o       = (const float*)d_in[9];
    const float* b_o       = (const float*)d_in[10];
    float* out = (float*)d_out;

    __half* gv;  float *gsoaw, *gmid;
    __half *wv, *wsa, *wo;
    cudaGetSymbolAddress((void**)&gv,    g_v);
    cudaGetSymbolAddress((void**)&gsoaw, g_soaw);
    cudaGetSymbolAddress((void**)&gmid,  g_mid);
    cudaGetSymbolAddress((void**)&wv,  g_wv);
    cudaGetSymbolAddress((void**)&wsa, g_wsa);
    cudaGetSymbolAddress((void**)&wo,  g_wo);

    const int gm = (M_ROWS + 127) / 128;  // 313

    // all weight transposes in one launch
    conv_w_all<<<448, 512>>>(W_v, W_so, W_aw, W_o);
    // fused G1 (v) + G2 (soaw)
    gemm_g12<<<dim3(4, gm), 256>>>(query, query_pos, wv, wsa, b_v, b_so, b_aw, gv, gsoaw);
    // deform (fp16 gathers, fp32 mid)
    deform_kernel<<<NQ, 256>>>(gv, gsoaw, refpts, gmid);
    // G3: out = mid @ W_o + b_o
    gemm_g3<<<dim3(2, gm), 256>>>(gmid, wo, b_o, out);
}